// round 1
// baseline (speedup 1.0000x reference)
#include <cuda_runtime.h>

// Uniform cubic B-spline evaluation.
// grid = linspace(-1,1,64) extended by 3 steps each side (h = 2/63).
// For x in [-1,1): interval j = floor((x+1)/h) in [0,62],
// out = sum_{r=0..3} w_r(u) * coeffs[j+r],  u = (x+1)/h - j.

__device__ __forceinline__ float eval_one(float x, const float4* __restrict__ tbl) {
    float t = (x + 1.0f) * 31.5f;          // 1/h = 63/2
    float jf = floorf(t);
    int j = (int)jf;
    j = min(max(j, 0), 62);                // safety clamp (x in [-1,1))
    float u = t - (float)j;
    const float sixth = 0.16666666666666666f;
    float om = 1.0f - u;
    float u2 = u * u;
    float u3 = u2 * u;
    float w0 = om * om * om * sixth;
    float w1 = (3.0f * u3 - 6.0f * u2 + 4.0f) * sixth;
    float w3 = u3 * sixth;
    float w2 = 1.0f - w0 - w1 - w3;        // partition of unity
    float4 c = tbl[j];
    return w0 * c.x + w1 * c.y + w2 * c.z + w3 * c.w;
}

__global__ void __launch_bounds__(256)
bspline_kernel(const float* __restrict__ x,
               const float* __restrict__ coeffs,
               float* __restrict__ out, int n4, int n) {
    __shared__ float  csh[72];
    __shared__ float4 tbl[63];
    int tid = threadIdx.x;
    if (tid < 72) csh[tid] = (tid < 69) ? coeffs[tid] : 0.0f;
    __syncthreads();
    if (tid < 63) tbl[tid] = make_float4(csh[tid], csh[tid + 1], csh[tid + 2], csh[tid + 3]);
    __syncthreads();

    const float4* __restrict__ x4 = (const float4*)x;
    float4* __restrict__ o4 = (float4*)out;
    int stride = gridDim.x * blockDim.x;
    for (int i = blockIdx.x * blockDim.x + tid; i < n4; i += stride) {
        float4 xv = x4[i];
        float4 ov;
        ov.x = eval_one(xv.x, tbl);
        ov.y = eval_one(xv.y, tbl);
        ov.z = eval_one(xv.z, tbl);
        ov.w = eval_one(xv.w, tbl);
        o4[i] = ov;
    }

    // scalar tail (N = 2^22 is divisible by 4; this is a safety net)
    int tail_start = n4 << 2;
    if (blockIdx.x == 0) {
        for (int i = tail_start + tid; i < n; i += blockDim.x)
            out[i] = eval_one(x[i], tbl);
    }
}

extern "C" void kernel_launch(void* const* d_in, const int* in_sizes, int n_in,
                              void* d_out, int out_size) {
    const float* x      = (const float*)d_in[0];
    const float* coeffs = (const float*)d_in[1];
    // d_in[2] = grid (uniform; recomputed analytically in-kernel, not needed)
    float* out = (float*)d_out;
    int n  = in_sizes[0];
    int n4 = n >> 2;
    int threads = 256;
    int blocks  = (n4 + threads - 1) / threads;
    if (blocks < 1) blocks = 1;
    bspline_kernel<<<blocks, threads>>>(x, coeffs, out, n4, n);
}

// round 2
// speedup vs baseline: 1.1603x; 1.1603x over previous
#include <cuda_runtime.h>

// Uniform cubic B-spline evaluation, bank-conflict-free shared gather.
// grid = linspace(-1,1,64) extended by 3 steps each side (h = 2/63).
// For x in [-1,1): j = floor((x+1)*31.5) in [0,62], u = frac,
// out = w0*c[j] + w1*c[j+1] + w2*c[j+2] + w3*c[j+3] (uniform cubic weights).
//
// Table tbl[j*8 + (lane&7)] = float4(c[j..j+3]) — 8-way replication across the
// eight 16B bank groups makes every LDS.128 quarter-warp phase conflict-free.

#define REP 8
#define NTBL 63

__device__ __forceinline__ float eval_one(float x, const float4* __restrict__ tbl, int rep) {
    float t = (x + 1.0f) * 31.5f;          // 1/h = 63/2
    float jf = floorf(t);
    int j = (int)jf;
    j = min(max(j, 0), 62);
    float u = t - (float)j;
    const float sixth = 0.16666666666666666f;
    float om = 1.0f - u;
    float u2 = u * u;
    float u3 = u2 * u;
    float w0 = om * om * om * sixth;
    float w1 = (3.0f * u3 - 6.0f * u2 + 4.0f) * sixth;
    float w3 = u3 * sixth;
    float w2 = 1.0f - w0 - w1 - w3;        // partition of unity
    float4 c = tbl[j * REP + rep];
    return w0 * c.x + w1 * c.y + w2 * c.z + w3 * c.w;
}

__global__ void __launch_bounds__(256)
bspline_kernel(const float4* __restrict__ x4,
               const float* __restrict__ coeffs,
               float4* __restrict__ o4, int n4) {
    __shared__ float  csh[72];
    __shared__ float4 tbl[NTBL * REP];
    int tid = threadIdx.x;
    if (tid < 72) csh[tid] = (tid < 69) ? coeffs[tid] : 0.0f;
    __syncthreads();
    #pragma unroll
    for (int e = tid; e < NTBL * REP; e += 256) {
        int j = e >> 3;
        tbl[e] = make_float4(csh[j], csh[j + 1], csh[j + 2], csh[j + 3]);
    }
    __syncthreads();

    const int rep = tid & (REP - 1);
    const int stride = gridDim.x * blockDim.x;

    // MLP=2: two independent float4 loads in flight per iteration.
    for (int i = blockIdx.x * blockDim.x + tid; i < n4; i += 2 * stride) {
        float4 xa = x4[i];
        int i2 = i + stride;
        bool has2 = (i2 < n4);
        float4 xb = has2 ? x4[i2] : make_float4(0.f, 0.f, 0.f, 0.f);

        float4 oa, ob;
        oa.x = eval_one(xa.x, tbl, rep);
        oa.y = eval_one(xa.y, tbl, rep);
        oa.z = eval_one(xa.z, tbl, rep);
        oa.w = eval_one(xa.w, tbl, rep);
        o4[i] = oa;

        if (has2) {
            ob.x = eval_one(xb.x, tbl, rep);
            ob.y = eval_one(xb.y, tbl, rep);
            ob.z = eval_one(xb.z, tbl, rep);
            ob.w = eval_one(xb.w, tbl, rep);
            o4[i2] = ob;
        }
    }
}

extern "C" void kernel_launch(void* const* d_in, const int* in_sizes, int n_in,
                              void* d_out, int out_size) {
    const float* x      = (const float*)d_in[0];
    const float* coeffs = (const float*)d_in[1];
    float* out = (float*)d_out;
    int n  = in_sizes[0];
    int n4 = n >> 2;                 // N = 2^22, divisible by 4
    int threads = 256;
    int blocks  = 592;               // 4 CTAs/SM resident, grid-stride
    int max_blocks = (n4 + threads - 1) / threads;
    if (blocks > max_blocks) blocks = max_blocks;
    if (blocks < 1) blocks = 1;
    bspline_kernel<<<blocks, threads>>>((const float4*)x, coeffs, (float4*)out, n4);
}